// round 4
// baseline (speedup 1.0000x reference)
#include <cuda_runtime.h>
#include <math.h>
#include <float.h>
#include <stdint.h>

// ---------------- problem constants ----------------
#define BEAM   5
#define TOPK   5
#define VOCAB  128000
#define HIST   511
#define NUM_KV 16
#define HEADS  8
#define SEQ    2048
#define HDIM   128

#define CHUNKS   25                  // stage-1 chunks per beam
#define TPB_SM   256
#define CHUNK_F4 (VOCAB/4/CHUNKS)    // 1280 float4 per chunk
#define F4_PER_T (CHUNK_F4/TPB_SM)   // 5 float4 per thread (exact)

#define NEG_SENTINEL (-FLT_MAX)      // finite sentinel: avoids (-INF)-(-INF)=NaN in merges

#define KV_ROW_ELEMS  (HEADS*SEQ*HDIM)          // 2,097,152 floats per (kv,beam)
#define KV_ROW4       (KV_ROW_ELEMS/4)          // 524,288 float4
#define KV_TOTAL      (NUM_KV*BEAM*KV_ROW_ELEMS)

// output layout (floats), in reference tuple order
#define OFF_SAVE   (KV_TOTAL)
#define OFF_RP     (OFF_SAVE + BEAM*(HIST+1))
#define OFF_PROB   (OFF_RP + BEAM*VOCAB)
#define OFF_TOK    (OFF_PROB + BEAM)
#define OFF_MAXIDX (OFF_TOK + BEAM)

// ---------------- device scratch ----------------
__device__ float g_pm[BEAM*CHUNKS];
__device__ float g_ps[BEAM*CHUNKS];
__device__ float g_pv[BEAM*CHUNKS*TOPK];
__device__ int   g_pi[BEAM*CHUNKS*TOPK];
__device__ int   g_beam_index[BEAM];
__device__ int   g_token[BEAM];

// ---------------- top-5 helpers (descending, ties -> lower index) ----------------
__device__ __forceinline__ void top5_insert(float* v, int* ix, float val, int idx) {
    if (val < v[TOPK-1]) return;
    if (val == v[TOPK-1] && idx >= ix[TOPK-1]) return;
    int p = TOPK - 1;
    #pragma unroll
    for (int q = TOPK - 1; q > 0; q--) {
        if (val > v[q-1] || (val == v[q-1] && idx < ix[q-1])) {
            v[q] = v[q-1]; ix[q] = ix[q-1]; p = q - 1;
        } else break;
    }
    v[p] = val; ix[p] = idx;
}

__device__ __forceinline__ void warp_merge(float* v, int* ix, float& m, float& s) {
    #pragma unroll
    for (int off = 16; off > 0; off >>= 1) {
        float pv[TOPK]; int pi[TOPK];
        #pragma unroll
        for (int j = 0; j < TOPK; j++) {
            pv[j] = __shfl_down_sync(0xffffffffu, v[j],  off);
            pi[j] = __shfl_down_sync(0xffffffffu, ix[j], off);
        }
        float pm = __shfl_down_sync(0xffffffffu, m, off);
        float ps = __shfl_down_sync(0xffffffffu, s, off);
        #pragma unroll
        for (int j = 0; j < TOPK; j++) top5_insert(v, ix, pv[j], pi[j]);
        float nm = fmaxf(m, pm);
        // m, pm are finite (NEG_SENTINEL, never -INF) -> m-nm finite, __expf well-defined
        s = s * __expf(m - nm) + ps * __expf(pm - nm);
        m = nm;
    }
}

// ---------------- kernel 1: per-(beam,chunk) partial logsumexp + top-5 ----------------
__global__ void __launch_bounds__(TPB_SM)
softmax_topk_kernel(const float4* __restrict__ logits, const float4* __restrict__ rpen) {
    const int c = blockIdx.x;            // chunk 0..24
    const int b = blockIdx.y;            // beam
    const int t = threadIdx.x;

    const float4* lg = logits + (size_t)b * (VOCAB/4) + c * CHUNK_F4;
    const float4* rp = rpen   + (size_t)b * (VOCAB/4) + c * CHUNK_F4;

    // -- phase A: 10 independent vector loads, products into registers --
    float4 xl[F4_PER_T], xr[F4_PER_T];
    #pragma unroll
    for (int k = 0; k < F4_PER_T; k++) xl[k] = __ldg(lg + k * TPB_SM + t);
    #pragma unroll
    for (int k = 0; k < F4_PER_T; k++) xr[k] = __ldg(rp + k * TPB_SM + t);

    float x[F4_PER_T*4];
    #pragma unroll
    for (int k = 0; k < F4_PER_T; k++) {
        x[k*4+0] = xl[k].x * xr[k].x;
        x[k*4+1] = xl[k].y * xr[k].y;
        x[k*4+2] = xl[k].z * xr[k].z;
        x[k*4+3] = xl[k].w * xr[k].w;
    }

    // -- phase B: branchless max, then sum of exp --
    float m = x[0];
    #pragma unroll
    for (int i = 1; i < F4_PER_T*4; i++) m = fmaxf(m, x[i]);
    float s = 0.0f;
    #pragma unroll
    for (int i = 0; i < F4_PER_T*4; i++) s += __expf(x[i] - m);

    // -- phase C: per-thread top-5 --
    float v[TOPK]; int ix[TOPK];
    #pragma unroll
    for (int j = 0; j < TOPK; j++) { v[j] = NEG_SENTINEL; ix[j] = 0x7FFFFFFF; }
    const int ebase = (c * CHUNK_F4) * 4;
    #pragma unroll
    for (int k = 0; k < F4_PER_T; k++) {
        #pragma unroll
        for (int e = 0; e < 4; e++) {
            int idx = ebase + (k * TPB_SM + t) * 4 + e;
            top5_insert(v, ix, x[k*4+e], idx);
        }
    }

    warp_merge(v, ix, m, s);

    __shared__ float sv[8][TOPK];
    __shared__ int   si[8][TOPK];
    __shared__ float sm[8], ss[8];
    const int warp = t >> 5;
    const int lane = t & 31;

    if (lane == 0) {
        #pragma unroll
        for (int j = 0; j < TOPK; j++) { sv[warp][j] = v[j]; si[warp][j] = ix[j]; }
        sm[warp] = m; ss[warp] = s;
    }
    __syncthreads();

    if (warp == 0) {
        if (lane < (TPB_SM >> 5)) {
            #pragma unroll
            for (int j = 0; j < TOPK; j++) { v[j] = sv[lane][j]; ix[j] = si[lane][j]; }
            m = sm[lane]; s = ss[lane];
        } else {
            #pragma unroll
            for (int j = 0; j < TOPK; j++) { v[j] = NEG_SENTINEL; ix[j] = 0x7FFFFFFF; }
            m = NEG_SENTINEL; s = 0.0f;   // finite sentinel: no NaN in merge
        }
        warp_merge(v, ix, m, s);
        if (lane == 0) {
            const int pc = b * CHUNKS + c;
            g_pm[pc] = m; g_ps[pc] = s;
            #pragma unroll
            for (int j = 0; j < TOPK; j++) {
                g_pv[pc*TOPK + j] = v[j];
                g_pi[pc*TOPK + j] = ix[j];
            }
        }
    }
}

// ---------------- kernel 2: merge partials + 25-candidate beam select ----------------
__global__ void combine_kernel(const float* __restrict__ prev_prob,
                               float* __restrict__ out_prob,
                               float* __restrict__ out_tok,
                               float* __restrict__ out_maxidx) {
    if (threadIdx.x != 0 || blockIdx.x != 0) return;

    float cur[BEAM*TOPK];
    int   ctok[BEAM*TOPK];

    for (int b = 0; b < BEAM; b++) {
        float v[TOPK]; int ix[TOPK];
        #pragma unroll
        for (int j = 0; j < TOPK; j++) { v[j] = NEG_SENTINEL; ix[j] = 0x7FFFFFFF; }
        float m = NEG_SENTINEL, s = 0.0f;
        for (int c = 0; c < CHUNKS; c++) {
            const int pc = b * CHUNKS + c;
            float pm = g_pm[pc], ps = g_ps[pc];
            float nm = fmaxf(m, pm);
            s = s * __expf(m - nm) + ps * __expf(pm - nm);
            m = nm;
            #pragma unroll
            for (int j = 0; j < TOPK; j++)
                top5_insert(v, ix, g_pv[pc*TOPK + j], g_pi[pc*TOPK + j]);
        }
        float lse = m + logf(s);
        float pp = prev_prob[b];
        #pragma unroll
        for (int j = 0; j < TOPK; j++) {
            cur[b*TOPK + j]  = v[j] - lse + pp;
            ctok[b*TOPK + j] = ix[j];
        }
    }

    bool used[BEAM*TOPK];
    #pragma unroll
    for (int i = 0; i < BEAM*TOPK; i++) used[i] = false;

    for (int k = 0; k < BEAM; k++) {
        int best = 0; float bv = -INFINITY;
        for (int i = 0; i < BEAM*TOPK; i++) {
            if (!used[i] && cur[i] > bv) { bv = cur[i]; best = i; }  // strict > => lowest index on ties
        }
        used[best] = true;
        int bi  = best / TOPK;
        int tok = ctok[best];
        g_beam_index[k] = bi;
        g_token[k]      = tok;
        out_prob[k]     = bv;
        out_tok[k]      = (float)tok;
        if (k == 0) out_maxidx[0] = (float)tok;
    }
}

// ---------------- kernel 3: fused gather (KV + repeat_penalty + save_id) ----------------
struct KvPtrs { const float4* p[NUM_KV]; };

#define KV_ROWS   (NUM_KV*BEAM)          // 80
#define RP_ROWS   3                      // ceil(160000/65536)
#define RP_F4     (BEAM*VOCAB/4)         // 160000
#define TPB       256
#define XBLK      256                    // 256*256 = 65536 threads per row

__global__ void __launch_bounds__(TPB)
gather_fused_kernel(KvPtrs kp,
                    const float* __restrict__ rpen,
                    const int*   __restrict__ save_id,
                    const float* __restrict__ pen,
                    float4* __restrict__ out) {
    const int row = blockIdx.y;

    if (row < KV_ROWS) {
        // ---- KV copy: 8 fully independent float4 loads per thread ----
        const int kv = row / BEAM;
        const int b  = row - kv * BEAM;
        const int bi = g_beam_index[b];

        const float4* __restrict__ src = kp.p[kv] + (size_t)bi * KV_ROW4;
        float4* __restrict__ dst = out + ((size_t)kv * BEAM + b) * KV_ROW4;

        const int j0 = blockIdx.x * TPB + threadIdx.x;   // 0..65535
        float4 vals[8];
        #pragma unroll
        for (int k = 0; k < 8; k++) vals[k] = __ldcg(src + j0 + k * 65536);
        #pragma unroll
        for (int k = 0; k < 8; k++) __stcs(dst + j0 + k * 65536, vals[k]);
        return;
    }

    if (row < KV_ROWS + RP_ROWS) {
        // ---- repeat_penalty gather (float4) + token penalty ----
        int t = (row - KV_ROWS) * 65536 + blockIdx.x * TPB + threadIdx.x;
        if (t >= RP_F4) return;
        int b  = t / (VOCAB/4);
        int v4 = t - b * (VOCAB/4);
        int bi = g_beam_index[b];
        float4 x = __ldcg((const float4*)rpen + (size_t)bi * (VOCAB/4) + v4);
        int tok = g_token[b];
        if ((tok >> 2) == v4) {
            float p = pen[0];
            ((float*)&x)[tok & 3] *= p;
        }
        float* o = (float*)out + OFF_RP;
        ((float4*)o)[t] = x;
        return;
    }

    // ---- save_id gather + token append ----
    int t = blockIdx.x * TPB + threadIdx.x;
    if (t >= BEAM * (HIST + 1)) return;
    int b = t / (HIST + 1);
    int j = t - b * (HIST + 1);
    int bi = g_beam_index[b];
    float* o = (float*)out + OFF_SAVE;
    o[t] = (j < HIST) ? (float)save_id[bi * HIST + j] : (float)g_token[b];
}

// ---------------- launch ----------------
extern "C" void kernel_launch(void* const* d_in, const int* in_sizes, int n_in,
                              void* d_out, int out_size) {
    (void)in_sizes; (void)n_in; (void)out_size;

    const int*   save_id = (const int*)  d_in[16];
    const float* rpen    = (const float*)d_in[17];
    const float* prev    = (const float*)d_in[18];
    // d_in[19] = batch_indices (arange, identity — unused)
    const float* logits  = (const float*)d_in[20];
    const float* pen     = (const float*)d_in[21];
    float* out = (float*)d_out;

    softmax_topk_kernel<<<dim3(CHUNKS, BEAM), TPB_SM>>>(
        (const float4*)logits, (const float4*)rpen);

    combine_kernel<<<1, 32>>>(prev, out + OFF_PROB, out + OFF_TOK, out + OFF_MAXIDX);

    KvPtrs kp;
    for (int i = 0; i < NUM_KV; i++) kp.p[i] = (const float4*)d_in[i];
    dim3 grid(XBLK, KV_ROWS + RP_ROWS + 1);
    gather_fused_kernel<<<grid, TPB>>>(kp, rpen, save_id, pen, (float4*)out);
}

// round 5
// speedup vs baseline: 1.1353x; 1.1353x over previous
#include <cuda_runtime.h>
#include <math.h>
#include <float.h>
#include <stdint.h>

// ---------------- problem constants ----------------
#define BEAM   5
#define TOPK   5
#define VOCAB  128000
#define HIST   511
#define NUM_KV 16
#define HEADS  8
#define SEQ    2048
#define HDIM   128

#define CHUNKS   125                 // stage-1 chunks per beam
#define TPB_SM   256
#define CHUNK_F4 (VOCAB/4/CHUNKS)    // 256 float4 per chunk
// 1 float4 per thread (exact): TPB_SM == CHUNK_F4

#define NEG_SENTINEL (-FLT_MAX)      // finite sentinel: avoids (-INF)-(-INF)=NaN in merges

#define KV_ROW_ELEMS  (HEADS*SEQ*HDIM)          // 2,097,152 floats per (kv,beam)
#define KV_ROW4       (KV_ROW_ELEMS/4)          // 524,288 float4
#define KV_TOTAL      (NUM_KV*BEAM*KV_ROW_ELEMS)

// output layout (floats), in reference tuple order
#define OFF_SAVE   (KV_TOTAL)
#define OFF_RP     (OFF_SAVE + BEAM*(HIST+1))
#define OFF_PROB   (OFF_RP + BEAM*VOCAB)
#define OFF_TOK    (OFF_PROB + BEAM)
#define OFF_MAXIDX (OFF_TOK + BEAM)

// ---------------- device scratch ----------------
__device__ float g_pm[BEAM*CHUNKS];
__device__ float g_ps[BEAM*CHUNKS];
__device__ float g_pv[BEAM*CHUNKS*TOPK];
__device__ int   g_pi[BEAM*CHUNKS*TOPK];
__device__ int   g_beam_index[BEAM];
__device__ int   g_token[BEAM];
__device__ unsigned int g_counter = 0;   // ticket for last-block combine (reset each run)

// ---------------- top-5 helpers (descending, ties -> lower index) ----------------
__device__ __forceinline__ void top5_insert(float* v, int* ix, float val, int idx) {
    if (val < v[TOPK-1]) return;
    if (val == v[TOPK-1] && idx >= ix[TOPK-1]) return;
    int p = TOPK - 1;
    #pragma unroll
    for (int q = TOPK - 1; q > 0; q--) {
        if (val > v[q-1] || (val == v[q-1] && idx < ix[q-1])) {
            v[q] = v[q-1]; ix[q] = ix[q-1]; p = q - 1;
        } else break;
    }
    v[p] = val; ix[p] = idx;
}

__device__ __forceinline__ void warp_merge(float* v, int* ix, float& m, float& s) {
    #pragma unroll
    for (int off = 16; off > 0; off >>= 1) {
        float pv[TOPK]; int pi[TOPK];
        #pragma unroll
        for (int j = 0; j < TOPK; j++) {
            pv[j] = __shfl_down_sync(0xffffffffu, v[j],  off);
            pi[j] = __shfl_down_sync(0xffffffffu, ix[j], off);
        }
        float pm = __shfl_down_sync(0xffffffffu, m, off);
        float ps = __shfl_down_sync(0xffffffffu, s, off);
        #pragma unroll
        for (int j = 0; j < TOPK; j++) top5_insert(v, ix, pv[j], pi[j]);
        float nm = fmaxf(m, pm);
        s = s * __expf(m - nm) + ps * __expf(pm - nm);   // finite sentinels, no NaN
        m = nm;
    }
}

// ---------------- kernel 1: partial logsumexp+top5, last block combines ----------------
__global__ void __launch_bounds__(TPB_SM)
softmax_topk_kernel(const float4* __restrict__ logits, const float4* __restrict__ rpen,
                    const float* __restrict__ prev_prob,
                    float* __restrict__ out_prob,
                    float* __restrict__ out_tok,
                    float* __restrict__ out_maxidx) {
    const int c = blockIdx.x;            // chunk 0..124
    const int b = blockIdx.y;            // beam
    const int t = threadIdx.x;
    const int warp = t >> 5;
    const int lane = t & 31;

    // -- phase A: one float4 of logits and rp per thread --
    const int f4i = c * CHUNK_F4 + t;
    float4 xl = __ldg(logits + (size_t)b * (VOCAB/4) + f4i);
    float4 xr = __ldg(rpen   + (size_t)b * (VOCAB/4) + f4i);
    float x[4];
    x[0] = xl.x * xr.x; x[1] = xl.y * xr.y; x[2] = xl.z * xr.z; x[3] = xl.w * xr.w;

    // -- phase B: branchless max, then sum of exp --
    float m = fmaxf(fmaxf(x[0], x[1]), fmaxf(x[2], x[3]));
    float s = __expf(x[0]-m) + __expf(x[1]-m) + __expf(x[2]-m) + __expf(x[3]-m);

    // -- phase C: per-thread top-5 (only 4 candidates) --
    float v[TOPK]; int ix[TOPK];
    #pragma unroll
    for (int j = 0; j < TOPK; j++) { v[j] = NEG_SENTINEL; ix[j] = 0x7FFFFFFF; }
    #pragma unroll
    for (int e = 0; e < 4; e++) top5_insert(v, ix, x[e], f4i*4 + e);

    warp_merge(v, ix, m, s);

    __shared__ float sv[8][TOPK];
    __shared__ int   si[8][TOPK];
    __shared__ float sm8[8], ss8[8];

    if (lane == 0) {
        #pragma unroll
        for (int j = 0; j < TOPK; j++) { sv[warp][j] = v[j]; si[warp][j] = ix[j]; }
        sm8[warp] = m; ss8[warp] = s;
    }
    __syncthreads();

    if (warp == 0) {
        if (lane < (TPB_SM >> 5)) {
            #pragma unroll
            for (int j = 0; j < TOPK; j++) { v[j] = sv[lane][j]; ix[j] = si[lane][j]; }
            m = sm8[lane]; s = ss8[lane];
        } else {
            #pragma unroll
            for (int j = 0; j < TOPK; j++) { v[j] = NEG_SENTINEL; ix[j] = 0x7FFFFFFF; }
            m = NEG_SENTINEL; s = 0.0f;
        }
        warp_merge(v, ix, m, s);
        if (lane == 0) {
            const int pc = b * CHUNKS + c;
            g_pm[pc] = m; g_ps[pc] = s;
            #pragma unroll
            for (int j = 0; j < TOPK; j++) {
                g_pv[pc*TOPK + j] = v[j];
                g_pi[pc*TOPK + j] = ix[j];
            }
        }
    }
    __syncthreads();

    // -- ticket: last block to finish performs the combine --
    __shared__ int s_last;
    if (t == 0) {
        __threadfence();
        unsigned int tk = atomicAdd(&g_counter, 1u);
        s_last = (tk == (unsigned)(CHUNKS*BEAM - 1));
    }
    __syncthreads();
    if (!s_last) return;

    // ================= combine (entire last block) =================
    __shared__ float s_cur[BEAM*TOPK];
    __shared__ int   s_ctok[BEAM*TOPK];

    if (warp < BEAM) {
        const int bb = warp;
        float cv[TOPK]; int cix[TOPK];
        #pragma unroll
        for (int j = 0; j < TOPK; j++) { cv[j] = NEG_SENTINEL; cix[j] = 0x7FFFFFFF; }
        float cm = NEG_SENTINEL, cs = 0.0f;
        for (int cc = lane; cc < CHUNKS; cc += 32) {
            const int pc = bb * CHUNKS + cc;
            float pm = g_pm[pc], ps = g_ps[pc];
            float nm = fmaxf(cm, pm);
            cs = cs * __expf(cm - nm) + ps * __expf(pm - nm);
            cm = nm;
            #pragma unroll
            for (int j = 0; j < TOPK; j++)
                top5_insert(cv, cix, g_pv[pc*TOPK + j], g_pi[pc*TOPK + j]);
        }
        warp_merge(cv, cix, cm, cs);
        if (lane == 0) {
            float lse = cm + logf(cs);
            float pp = prev_prob[bb];
            #pragma unroll
            for (int j = 0; j < TOPK; j++) {
                s_cur[bb*TOPK + j]  = cv[j] - lse + pp;
                s_ctok[bb*TOPK + j] = cix[j];
            }
        }
    }
    __syncthreads();

    if (t == 0) {
        bool used[BEAM*TOPK];
        #pragma unroll
        for (int i = 0; i < BEAM*TOPK; i++) used[i] = false;
        for (int k = 0; k < BEAM; k++) {
            int best = 0; float bv = -INFINITY;
            for (int i = 0; i < BEAM*TOPK; i++) {
                if (!used[i] && s_cur[i] > bv) { bv = s_cur[i]; best = i; }  // strict > => lowest idx on ties
            }
            used[best] = true;
            int bi  = best / TOPK;
            int tok = s_ctok[best];
            g_beam_index[k] = bi;
            g_token[k]      = tok;
            out_prob[k]     = bv;
            out_tok[k]      = (float)tok;
            if (k == 0) out_maxidx[0] = (float)tok;
        }
        g_counter = 0;   // reset for next graph replay (deterministic)
        __threadfence();
    }
}

// ---------------- kernel 2: fused gather (KV + repeat_penalty + save_id) ----------------
struct KvPtrs { const float4* p[NUM_KV]; };

#define KV_ROWS   (NUM_KV*BEAM)          // 80
#define RP_ROWS   3                      // ceil(160000/65536)
#define RP_F4     (BEAM*VOCAB/4)         // 160000
#define TPB       256
#define XBLK      256                    // 256*256 = 65536 threads per row

__global__ void __launch_bounds__(TPB)
gather_fused_kernel(KvPtrs kp,
                    const float* __restrict__ rpen,
                    const int*   __restrict__ save_id,
                    const float* __restrict__ pen,
                    float4* __restrict__ out) {
    const int row = blockIdx.y;

    if (row < KV_ROWS) {
        // ---- KV copy: 8 fully independent float4 loads per thread ----
        const int kv = row / BEAM;
        const int b  = row - kv * BEAM;
        const int bi = g_beam_index[b];

        const float4* __restrict__ src = kp.p[kv] + (size_t)bi * KV_ROW4;
        float4* __restrict__ dst = out + ((size_t)kv * BEAM + b) * KV_ROW4;

        const int j0 = blockIdx.x * TPB + threadIdx.x;   // 0..65535
        float4 vals[8];
        #pragma unroll
        for (int k = 0; k < 8; k++) vals[k] = __ldcg(src + j0 + k * 65536);
        #pragma unroll
        for (int k = 0; k < 8; k++) __stcs(dst + j0 + k * 65536, vals[k]);
        return;
    }

    if (row < KV_ROWS + RP_ROWS) {
        // ---- repeat_penalty gather (float4) + token penalty ----
        int t = (row - KV_ROWS) * 65536 + blockIdx.x * TPB + threadIdx.x;
        if (t >= RP_F4) return;
        int b  = t / (VOCAB/4);
        int v4 = t - b * (VOCAB/4);
        int bi = g_beam_index[b];
        float4 x = __ldcg((const float4*)rpen + (size_t)bi * (VOCAB/4) + v4);
        int tok = g_token[b];
        if ((tok >> 2) == v4) {
            float p = pen[0];
            ((float*)&x)[tok & 3] *= p;
        }
        float* o = (float*)out + OFF_RP;
        ((float4*)o)[t] = x;
        return;
    }

    // ---- save_id gather + token append ----
    int t = blockIdx.x * TPB + threadIdx.x;
    if (t >= BEAM * (HIST + 1)) return;
    int b = t / (HIST + 1);
    int j = t - b * (HIST + 1);
    int bi = g_beam_index[b];
    float* o = (float*)out + OFF_SAVE;
    o[t] = (j < HIST) ? (float)save_id[bi * HIST + j] : (float)g_token[b];
}

// ---------------- launch ----------------
extern "C" void kernel_launch(void* const* d_in, const int* in_sizes, int n_in,
                              void* d_out, int out_size) {
    (void)in_sizes; (void)n_in; (void)out_size;

    const int*   save_id = (const int*)  d_in[16];
    const float* rpen    = (const float*)d_in[17];
    const float* prev    = (const float*)d_in[18];
    // d_in[19] = batch_indices (arange, identity — unused)
    const float* logits  = (const float*)d_in[20];
    const float* pen     = (const float*)d_in[21];
    float* out = (float*)d_out;

    softmax_topk_kernel<<<dim3(CHUNKS, BEAM), TPB_SM>>>(
        (const float4*)logits, (const float4*)rpen, prev,
        out + OFF_PROB, out + OFF_TOK, out + OFF_MAXIDX);

    KvPtrs kp;
    for (int i = 0; i < NUM_KV; i++) kp.p[i] = (const float4*)d_in[i];
    dim3 grid(XBLK, KV_ROWS + RP_ROWS + 1);
    gather_fused_kernel<<<grid, TPB>>>(kp, rpen, save_id, pen, (float4*)out);
}